// round 1
// baseline (speedup 1.0000x reference)
#include <cuda_runtime.h>
#include <math.h>
#include <stdint.h>

// Problem constants
#define HB    1024
#define EB    2048
#define SB    128
#define NUV   4224      // 2*E + S
#define NSEQ  512
#define NBATCH 32
#define MTOT  16384     // B*N

// ---------------------------------------------------------------------------
// Scratch (static __device__ globals per harness rules; ~530 MB total)
// ---------------------------------------------------------------------------
__device__ __align__(128) float g_xn [(size_t)MTOT * HB];            //  64 MB
__device__ __align__(128) float g_uv [(size_t)MTOT * NUV];           // 277 MB
__device__ __align__(128) float g_q  [(size_t)NBATCH * NSEQ * SB];   //   8 MB
__device__ __align__(128) float g_kt [(size_t)NBATCH * SB * NSEQ];   //   8 MB
__device__ __align__(128) float g_ker[(size_t)NBATCH * NSEQ * NSEQ]; //  33 MB
__device__ __align__(128) float g_att[(size_t)MTOT * EB];            // 134 MB
__device__ __align__(128) float g_trig[NSEQ * 64 * 2];

// ---------------------------------------------------------------------------
// LayerNorm: one block per row (1024 floats), 256 threads, float4
// ---------------------------------------------------------------------------
__global__ void ln_kernel(const float* __restrict__ x,
                          const float* __restrict__ g,
                          const float* __restrict__ b,
                          float* __restrict__ out)
{
    int row = blockIdx.x;
    const float4* xr = (const float4*)(x + (size_t)row * HB);
    float4 v = xr[threadIdx.x];
    float s  = v.x + v.y + v.z + v.w;
    float sq = v.x*v.x + v.y*v.y + v.z*v.z + v.w*v.w;

    #pragma unroll
    for (int o = 16; o; o >>= 1) {
        s  += __shfl_xor_sync(0xffffffffu, s,  o);
        sq += __shfl_xor_sync(0xffffffffu, sq, o);
    }
    __shared__ float ss[8], sqs[8];
    int w = threadIdx.x >> 5, l = threadIdx.x & 31;
    if (l == 0) { ss[w] = s; sqs[w] = sq; }
    __syncthreads();
    float st = 0.f, sqt = 0.f;
    #pragma unroll
    for (int i = 0; i < 8; i++) { st += ss[i]; sqt += sqs[i]; }

    float mu  = st  * (1.f / HB);
    float var = sqt * (1.f / HB) - mu * mu;
    float rs  = rsqrtf(var + 1e-5f);

    float4 gg = ((const float4*)g)[threadIdx.x];
    float4 bb = ((const float4*)b)[threadIdx.x];
    float4 o;
    o.x = (v.x - mu) * rs * gg.x + bb.x;
    o.y = (v.y - mu) * rs * gg.y + bb.y;
    o.z = (v.z - mu) * rs * gg.z + bb.z;
    o.w = (v.w - mu) * rs * gg.w + bb.w;
    ((float4*)(out + (size_t)row * HB))[threadIdx.x] = o;
}

// ---------------------------------------------------------------------------
// RoPE trig table: cos/sin for (pos, freq) with f32 argument path emulated.
// inv_freq correctly-rounded f32 via double pow; arg = f32(pos)*f32(inv);
// sin/cos evaluated in double AT that f32 argument (matches ref pipeline).
// ---------------------------------------------------------------------------
__global__ void trig_kernel(float* __restrict__ tab)
{
    int idx = blockIdx.x * blockDim.x + threadIdx.x;
    if (idx >= NSEQ * 64) return;
    int n = idx >> 6, i = idx & 63;
    double inv = pow(10000.0, (double)i * (1.0 / 64.0));
    float invf = (float)inv;
    float arg  = (float)n * invf;
    tab[2*idx]     = (float)cos((double)arg);
    tab[2*idx + 1] = (float)sin((double)arg);
}

// ---------------------------------------------------------------------------
// Build q [b][n][d] and k^T [b][d][n] from silu'd base slice of uv
// ---------------------------------------------------------------------------
__global__ void qk_kernel(const float* __restrict__ gamma,
                          const float* __restrict__ beta,
                          const float* __restrict__ trig,
                          const float* __restrict__ uv,
                          float* __restrict__ q,
                          float* __restrict__ kt)
{
    int p = blockIdx.x;            // 0..16383 (b*512 + n)
    int n = p & (NSEQ - 1);
    int b = p >> 9;
    int d = threadIdx.x;           // 0..127

    __shared__ float sb[SB];
    sb[d] = uv[(size_t)p * NUV + 2 * EB + d];
    __syncthreads();

    int i  = d & 63;
    float c = trig[2 * (n * 64 + i)];
    float s = trig[2 * (n * 64 + i) + 1];
    int dp = d ^ 64;

    float own_q = sb[d]  * gamma[d]        + beta[d];
    float par_q = sb[dp] * gamma[dp]       + beta[dp];
    float own_k = sb[d]  * gamma[128 + d]  + beta[128 + d];
    float par_k = sb[dp] * gamma[128 + dp] + beta[128 + dp];

    float qv, kv;
    if (d < 64) { qv = own_q * c - par_q * s; kv = own_k * c - par_k * s; }
    else        { qv = own_q * c + par_q * s; kv = own_k * c + par_k * s; }

    q [(size_t)p * SB + d]                  = qv;
    kt[((size_t)b * SB + d) * NSEQ + n]     = kv;
}

// ---------------------------------------------------------------------------
// Generic fp32 SGEMM, 128x128x8 tiles, 8x8 microtile, 256 threads,
// register-staged software pipeline. Template MODE selects fused epilogue:
//   0: +bias then silu                      (aux1 = uv_b)
//   1: * U[row][col]                        (aux1 = u base, batAux/ldaux)
//   2: +bias[col] + shortcut[row][col]      (aux1 = o_b, aux2 = x, ldaux)
//   3: relu(acc/512 + w[col-row+511] + (1-mask[col])*-1e12)^2
//                                           (aux1 = w, aux2 = mask, batAux)
// ---------------------------------------------------------------------------
#define BM 128
#define BN 128
#define BKK 8

template<int MODE>
__global__ __launch_bounds__(256, 2)
void sgemm_kernel(const float* __restrict__ A, const float* __restrict__ B,
                  float* __restrict__ C, int Md, int Nd, int Kd,
                  int lda, int ldb, int ldc,
                  long batA, long batB, long batC,
                  const float* __restrict__ aux1, const float* __restrict__ aux2,
                  long batAux, int ldaux)
{
    int bz = blockIdx.z;
    A += (size_t)bz * batA;
    B += (size_t)bz * batB;
    C += (size_t)bz * batC;

    const int tid   = threadIdx.x;
    const int tileN = blockIdx.x * BN;
    const int tileM = blockIdx.y * BM;

    __shared__ float As[BKK][BM];
    __shared__ float Bs[BKK][BN];

    const int arow = tid >> 1;
    const int acol = (tid & 1) * 4;
    const int brow = tid >> 5;
    const int bcol = (tid & 31) * 4;

    const float* Aptr = A + (size_t)(tileM + arow) * lda + acol;
    const float* Bptr = B + (size_t)brow * ldb + tileN + bcol;

    const int ty = tid >> 4;   // 0..15
    const int tx = tid & 15;

    float acc[8][8];
    #pragma unroll
    for (int i = 0; i < 8; i++)
        #pragma unroll
        for (int j = 0; j < 8; j++) acc[i][j] = 0.f;

    float4 aReg = *(const float4*)Aptr;
    float4 bReg = *(const float4*)Bptr;

    const int nkt = Kd / BKK;
    for (int kt = 0; kt < nkt; ++kt) {
        As[acol + 0][arow] = aReg.x;
        As[acol + 1][arow] = aReg.y;
        As[acol + 2][arow] = aReg.z;
        As[acol + 3][arow] = aReg.w;
        *(float4*)&Bs[brow][bcol] = bReg;
        __syncthreads();

        if (kt + 1 < nkt) {
            aReg = *(const float4*)(Aptr + (size_t)(kt + 1) * BKK);
            bReg = *(const float4*)(Bptr + (size_t)(kt + 1) * BKK * ldb);
        }

        #pragma unroll
        for (int k = 0; k < BKK; ++k) {
            float4 a0 = *(const float4*)&As[k][ty * 4];
            float4 a1 = *(const float4*)&As[k][64 + ty * 4];
            float4 b0 = *(const float4*)&Bs[k][tx * 4];
            float4 b1 = *(const float4*)&Bs[k][64 + tx * 4];
            float av[8] = {a0.x, a0.y, a0.z, a0.w, a1.x, a1.y, a1.z, a1.w};
            float bv[8] = {b0.x, b0.y, b0.z, b0.w, b1.x, b1.y, b1.z, b1.w};
            #pragma unroll
            for (int i = 0; i < 8; i++)
                #pragma unroll
                for (int j = 0; j < 8; j++)
                    acc[i][j] = fmaf(av[i], bv[j], acc[i][j]);
        }
        __syncthreads();
    }

    // Epilogue
    const float* Uptr  = (MODE == 1) ? aux1 + (size_t)bz * batAux : nullptr;
    const float* maskp = (MODE == 3) ? aux2 + (size_t)bz * batAux : nullptr;

    #pragma unroll
    for (int ii = 0; ii < 2; ii++) {
        #pragma unroll
        for (int i = 0; i < 4; i++) {
            int grow = tileM + ii * 64 + ty * 4 + i;
            #pragma unroll
            for (int jj = 0; jj < 2; jj++) {
                int gcol0 = tileN + jj * 64 + tx * 4;
                float vals[4];
                #pragma unroll
                for (int j2 = 0; j2 < 4; j2++) vals[j2] = acc[ii * 4 + i][jj * 4 + j2];
                #pragma unroll
                for (int j2 = 0; j2 < 4; j2++) {
                    int col = gcol0 + j2;
                    float v = vals[j2];
                    if (MODE == 0) {
                        v += aux1[col];
                        v = v / (1.f + expf(-v));
                    } else if (MODE == 1) {
                        v *= Uptr[(size_t)grow * ldaux + col];
                    } else if (MODE == 2) {
                        v += aux1[col] + aux2[(size_t)grow * ldaux + col];
                    } else { // MODE 3
                        float t = v * (1.0f / 512.0f)
                                + aux1[col - grow + 511]
                                + (1.f - maskp[col]) * (-1e12f);
                        t = fmaxf(t, 0.f);
                        v = t * t;
                    }
                    vals[j2] = v;
                }
                float4 r = make_float4(vals[0], vals[1], vals[2], vals[3]);
                *(float4*)&C[(size_t)grow * ldc + gcol0] = r;
            }
        }
    }
}

// ---------------------------------------------------------------------------
// Launch
// ---------------------------------------------------------------------------
extern "C" void kernel_launch(void* const* d_in, const int* in_sizes, int n_in,
                              void* d_out, int out_size)
{
    const float* x     = (const float*)d_in[0];
    const float* amask = (const float*)d_in[1];
    const float* gamma = (const float*)d_in[2];
    const float* beta  = (const float*)d_in[3];
    const float* w     = (const float*)d_in[4];
    // d_in[5] = a_p, d_in[6] = b_p : unused by the reference
    const float* uv_w  = (const float*)d_in[7];
    const float* uv_b  = (const float*)d_in[8];
    const float* o_w   = (const float*)d_in[9];
    const float* o_b   = (const float*)d_in[10];
    const float* ln_g  = (const float*)d_in[11];
    const float* ln_b  = (const float*)d_in[12];
    float* out = (float*)d_out;

    float *xn, *uv, *q, *kt, *ker, *att, *trig;
    cudaGetSymbolAddress((void**)&xn,   g_xn);
    cudaGetSymbolAddress((void**)&uv,   g_uv);
    cudaGetSymbolAddress((void**)&q,    g_q);
    cudaGetSymbolAddress((void**)&kt,   g_kt);
    cudaGetSymbolAddress((void**)&ker,  g_ker);
    cudaGetSymbolAddress((void**)&att,  g_att);
    cudaGetSymbolAddress((void**)&trig, g_trig);

    // 1) LayerNorm
    ln_kernel<<<MTOT, 256>>>(x, ln_g, ln_b, xn);

    // 2) RoPE trig table (tiny)
    trig_kernel<<<(NSEQ * 64 + 255) / 256, 256>>>(trig);

    // 3) uv = silu(xn @ uv_w + uv_b)   [16384 x 4224, K=1024]
    sgemm_kernel<0><<<dim3(NUV / BN, MTOT / BM, 1), 256>>>(
        xn, uv_w, uv, MTOT, NUV, HB, HB, NUV, NUV,
        0L, 0L, 0L, uv_b, nullptr, 0L, 0);

    // 4) q / k^T with gamma/beta + RoPE
    qk_kernel<<<MTOT, 128>>>(gamma, beta, trig, uv, q, kt);

    // 5) ker = relu(q@k^T/512 + relbias + maskbias)^2   per batch [512x512, K=128]
    sgemm_kernel<3><<<dim3(NSEQ / BN, NSEQ / BM, NBATCH), 256>>>(
        q, kt, ker, NSEQ, NSEQ, SB, SB, NSEQ, NSEQ,
        (long)NSEQ * SB, (long)SB * NSEQ, (long)NSEQ * NSEQ,
        w, amask, (long)NSEQ, 0);

    // 6) att = u * (ker @ v)   per batch [512x2048, K=512]
    sgemm_kernel<1><<<dim3(EB / BN, NSEQ / BM, NBATCH), 256>>>(
        ker, uv + EB, att, NSEQ, EB, NSEQ, NSEQ, NUV, EB,
        (long)NSEQ * NSEQ, (long)NSEQ * NUV, (long)NSEQ * EB,
        uv, nullptr, (long)NSEQ * NUV, NUV);

    // 7) out = att @ o_w + o_b + x   [16384 x 1024, K=2048]
    sgemm_kernel<2><<<dim3(HB / BN, MTOT / BM, 1), 256>>>(
        att, o_w, out, MTOT, HB, EB, EB, HB, HB,
        0L, 0L, 0L, o_b, x, 0L, HB);
}

// round 5
// speedup vs baseline: 1.8102x; 1.8102x over previous
#include <cuda_runtime.h>
#include <cuda_bf16.h>
#include <math.h>
#include <stdint.h>

#define HB    1024
#define EB    2048
#define SB    128
#define NUV   4224
#define NSEQ  512
#define NBATCH 32
#define MTOT  16384

typedef __nv_bfloat16 bf16;

// ---------------------------------------------------------------------------
// Scratch
// ---------------------------------------------------------------------------
__device__ __align__(128) bf16 g_xnh [(size_t)MTOT * HB];
__device__ __align__(128) bf16 g_xnl [(size_t)MTOT * HB];
__device__ __align__(128) bf16 g_uvwh[(size_t)NUV * HB];
__device__ __align__(128) bf16 g_uvwl[(size_t)NUV * HB];
__device__ __align__(128) bf16 g_owh [(size_t)HB * EB];
__device__ __align__(128) bf16 g_owl [(size_t)HB * EB];
__device__ __align__(128) bf16 g_uvh [(size_t)MTOT * NUV];
__device__ __align__(128) bf16 g_uvl [(size_t)MTOT * NUV];
__device__ __align__(128) bf16 g_qh  [(size_t)MTOT * SB];
__device__ __align__(128) bf16 g_ql  [(size_t)MTOT * SB];
__device__ __align__(128) bf16 g_kh  [(size_t)MTOT * SB];
__device__ __align__(128) bf16 g_kl  [(size_t)MTOT * SB];
__device__ __align__(128) bf16 g_kerh[(size_t)NBATCH * NSEQ * NSEQ];
__device__ __align__(128) bf16 g_kerl[(size_t)NBATCH * NSEQ * NSEQ];
__device__ __align__(128) bf16 g_vth [(size_t)NBATCH * EB * NSEQ];
__device__ __align__(128) bf16 g_vtl [(size_t)NBATCH * EB * NSEQ];
__device__ __align__(128) bf16 g_atth[(size_t)MTOT * EB];
__device__ __align__(128) bf16 g_attl[(size_t)MTOT * EB];
__device__ __align__(128) float g_trig[NSEQ * 64 * 2];

// ---------------------------------------------------------------------------
// Helpers
// ---------------------------------------------------------------------------
__device__ __forceinline__ uint32_t smem_u32(const void* p) {
    uint32_t a;
    asm("{ .reg .u64 t; cvta.to.shared.u64 t, %1; cvt.u32.u64 %0, t; }" : "=r"(a) : "l"(p));
    return a;
}
__device__ __forceinline__ uint32_t lds32(uint32_t a) {
    uint32_t v;
    asm volatile("ld.shared.b32 %0, [%1];" : "=r"(v) : "r"(a));
    return v;
}
__device__ __forceinline__ void mma16816(float* d, const uint32_t* a, const uint32_t* b) {
    asm volatile(
        "mma.sync.aligned.m16n8k16.row.col.f32.bf16.bf16.f32 "
        "{%0,%1,%2,%3}, {%4,%5,%6,%7}, {%8,%9}, {%0,%1,%2,%3};"
        : "+f"(d[0]), "+f"(d[1]), "+f"(d[2]), "+f"(d[3])
        : "r"(a[0]), "r"(a[1]), "r"(a[2]), "r"(a[3]), "r"(b[0]), "r"(b[1]));
}
__device__ __forceinline__ void split2(float v, bf16& h, bf16& l) {
    h = __float2bfloat16(v);
    l = __float2bfloat16(v - __bfloat162float(h));
}
__device__ __forceinline__ uint32_t pack_bf2(bf16 a, bf16 b) {
    return (uint32_t)__bfloat16_as_ushort(a) | ((uint32_t)__bfloat16_as_ushort(b) << 16);
}

// ---------------------------------------------------------------------------
// LayerNorm -> hi/lo bf16
// ---------------------------------------------------------------------------
__global__ void ln_kernel(const float* __restrict__ x, const float* __restrict__ g,
                          const float* __restrict__ b,
                          bf16* __restrict__ oh, bf16* __restrict__ ol)
{
    int row = blockIdx.x;
    float4 v = ((const float4*)(x + (size_t)row * HB))[threadIdx.x];
    float s = v.x + v.y + v.z + v.w;
    float sq = v.x*v.x + v.y*v.y + v.z*v.z + v.w*v.w;
    #pragma unroll
    for (int o = 16; o; o >>= 1) {
        s  += __shfl_xor_sync(0xffffffffu, s, o);
        sq += __shfl_xor_sync(0xffffffffu, sq, o);
    }
    __shared__ float ss[8], sqs[8];
    int w = threadIdx.x >> 5, l = threadIdx.x & 31;
    if (l == 0) { ss[w] = s; sqs[w] = sq; }
    __syncthreads();
    float st = 0.f, sqt = 0.f;
    #pragma unroll
    for (int i = 0; i < 8; i++) { st += ss[i]; sqt += sqs[i]; }
    float mu = st * (1.f / HB);
    float var = sqt * (1.f / HB) - mu * mu;
    float rs = rsqrtf(var + 1e-5f);
    float4 gg = ((const float4*)g)[threadIdx.x];
    float4 bb = ((const float4*)b)[threadIdx.x];
    float vv[4] = {v.x, v.y, v.z, v.w};
    float gv[4] = {gg.x, gg.y, gg.z, gg.w};
    float bv[4] = {bb.x, bb.y, bb.z, bb.w};
    size_t base = (size_t)row * HB + threadIdx.x * 4;
    #pragma unroll
    for (int j = 0; j < 4; j++) {
        float o = (vv[j] - mu) * rs * gv[j] + bv[j];
        bf16 h, lo; split2(o, h, lo);
        oh[base + j] = h; ol[base + j] = lo;
    }
}

// ---------------------------------------------------------------------------
// RoPE trig table
// ---------------------------------------------------------------------------
__global__ void trig_kernel(float* __restrict__ tab)
{
    int idx = blockIdx.x * blockDim.x + threadIdx.x;
    if (idx >= NSEQ * 64) return;
    int n = idx >> 6, i = idx & 63;
    double inv = pow(10000.0, (double)i * (1.0 / 64.0));
    float arg = (float)n * (float)inv;
    tab[2 * idx]     = (float)cos((double)arg);
    tab[2 * idx + 1] = (float)sin((double)arg);
}

// ---------------------------------------------------------------------------
// Weight transpose + split: W[K,N] f32 -> T[N,K] hi/lo bf16
// ---------------------------------------------------------------------------
__global__ void tsplit_kernel(const float* __restrict__ W, int K, int N,
                              bf16* __restrict__ Th, bf16* __restrict__ Tl)
{
    __shared__ float t[32][33];
    int n0 = blockIdx.x * 32, k0 = blockIdx.y * 32;
    int tx = threadIdx.x, ty = threadIdx.y;
    #pragma unroll
    for (int i = 0; i < 32; i += 8)
        t[ty + i][tx] = W[(size_t)(k0 + ty + i) * N + (n0 + tx)];
    __syncthreads();
    #pragma unroll
    for (int i = 0; i < 32; i += 8) {
        float v = t[tx][ty + i];
        bf16 h, l; split2(v, h, l);
        size_t o = (size_t)(n0 + ty + i) * K + (k0 + tx);
        Th[o] = h; Tl[o] = l;
    }
}

// ---------------------------------------------------------------------------
// v transpose (bf16 hi/lo): uv[:, E:2E] per batch -> vT[b][e][s]
// ---------------------------------------------------------------------------
__global__ void vtrans_kernel(const bf16* __restrict__ uvh, const bf16* __restrict__ uvl,
                              bf16* __restrict__ vTh, bf16* __restrict__ vTl)
{
    __shared__ bf16 th[32][33], tl[32][33];
    int b = blockIdx.z;
    int s0 = blockIdx.x * 32, e0 = blockIdx.y * 32;
    int tx = threadIdx.x, ty = threadIdx.y;
    #pragma unroll
    for (int i = 0; i < 32; i += 8) {
        size_t src = ((size_t)(b * NSEQ + s0 + ty + i)) * NUV + EB + e0 + tx;
        th[ty + i][tx] = uvh[src];
        tl[ty + i][tx] = uvl[src];
    }
    __syncthreads();
    #pragma unroll
    for (int i = 0; i < 32; i += 8) {
        size_t dst = ((size_t)b * EB + e0 + ty + i) * NSEQ + (s0 + tx);
        vTh[dst] = th[tx][ty + i];
        vTl[dst] = tl[tx][ty + i];
    }
}

// ---------------------------------------------------------------------------
// q/k build with gamma/beta + RoPE -> hi/lo bf16
// ---------------------------------------------------------------------------
__global__ void qk_kernel(const float* __restrict__ gamma, const float* __restrict__ beta,
                          const float* __restrict__ trig,
                          const bf16* __restrict__ uvh, const bf16* __restrict__ uvl,
                          bf16* __restrict__ qh, bf16* __restrict__ ql,
                          bf16* __restrict__ kh, bf16* __restrict__ kl)
{
    int p = blockIdx.x;
    int n = p & (NSEQ - 1);
    int d = threadIdx.x;
    __shared__ float sb[SB];
    size_t src = (size_t)p * NUV + 2 * EB + d;
    sb[d] = __bfloat162float(uvh[src]) + __bfloat162float(uvl[src]);
    __syncthreads();
    int i = d & 63;
    float c = trig[2 * (n * 64 + i)];
    float s = trig[2 * (n * 64 + i) + 1];
    int dp = d ^ 64;
    float own_q = sb[d]  * gamma[d]       + beta[d];
    float par_q = sb[dp] * gamma[dp]      + beta[dp];
    float own_k = sb[d]  * gamma[128 + d]  + beta[128 + d];
    float par_k = sb[dp] * gamma[128 + dp] + beta[128 + dp];
    float qv, kv;
    if (d < 64) { qv = own_q * c - par_q * s; kv = own_k * c - par_k * s; }
    else        { qv = own_q * c + par_q * s; kv = own_k * c + par_k * s; }
    size_t o = (size_t)p * SB + d;
    bf16 h, l;
    split2(qv, h, l); qh[o] = h; ql[o] = l;
    split2(kv, h, l); kh[o] = h; kl[o] = l;
}

// ---------------------------------------------------------------------------
// Split-bf16 GEMM via mma.sync (HMMA). CTA 256x128, BK=32, 8 warps (4Mx2N),
// warp tile 64x64. 3-stage cp.async pipeline. A[M,K], B[N,K] (both K-major),
// hi/lo operands -> 3 passes (hh, hl, lh) into f32 accumulators.
// MODE 0: silu(acc+aux1[col]) -> split      MODE 1: acc * (Uh+Ul)[row][col] -> split
// MODE 2: acc+aux1[col]+aux2[row][col]->f32 MODE 3: relu(acc/512+w+mask)^2 -> split
// ---------------------------------------------------------------------------
#define ROWB 80                   // smem row stride (bytes) for a 32-elem bf16 row
#define OFF_AH 0                  // 256 rows
#define OFF_AL (256 * ROWB)
#define OFF_BH (512 * ROWB)       // 128 rows
#define OFF_BL (640 * ROWB)
#define STAGE_B (768 * ROWB)      // 61440 bytes
#define SMEM_MM (3 * STAGE_B)     // 184320 bytes

template<int R>
__device__ __forceinline__ void load_tile80(uint32_t sdst, const bf16* gp, int ld, int tid)
{
    #pragma unroll
    for (int it = 0; it < R * 4 / 256; ++it) {
        int idx = it * 256 + tid;
        int row = idx >> 2, c = idx & 3;
        asm volatile("cp.async.cg.shared.global [%0], [%1], 16;"
            :: "r"(sdst + row * ROWB + c * 16), "l"(gp + (size_t)row * ld + c * 8));
    }
}

template<int MODE>
__global__ __launch_bounds__(256, 1)
void mm_kernel(const bf16* __restrict__ Ah, const bf16* __restrict__ Al,
               const bf16* __restrict__ Bh, const bf16* __restrict__ Bl,
               int Kd, int lda, int ldb, int ldc,
               long batA, long batB, long batC,
               float* __restrict__ Cf, bf16* __restrict__ Ch, bf16* __restrict__ Cl,
               const float* __restrict__ aux1, const float* __restrict__ aux2,
               long batAux, int ldaux,
               const bf16* __restrict__ Uh, const bf16* __restrict__ Ul,
               long batU, int ldU)
{
    extern __shared__ __align__(128) char smem[];
    const uint32_t sbase = smem_u32(smem);
    const int tid = threadIdx.x, lane = tid & 31, w = tid >> 5;
    const int wm = w >> 1, wn = w & 1;
    const int g = lane >> 2, t2 = (lane & 3) * 2;
    const int bz = blockIdx.z;
    const int tileM = blockIdx.y * 256, tileN = blockIdx.x * 128;

    const bf16* pAh = Ah + (size_t)bz * batA + (size_t)tileM * lda;
    const bf16* pAl = Al + (size_t)bz * batA + (size_t)tileM * lda;
    const bf16* pBh = Bh + (size_t)bz * batB + (size_t)tileN * ldb;
    const bf16* pBl = Bl + (size_t)bz * batB + (size_t)tileN * ldb;

    const int nk = Kd / 32;

    // prologue: stages 0,1
    #pragma unroll
    for (int p = 0; p < 2; ++p) {
        uint32_t sb = sbase + p * STAGE_B;
        load_tile80<256>(sb + OFF_AH, pAh + p * 32, lda, tid);
        load_tile80<256>(sb + OFF_AL, pAl + p * 32, lda, tid);
        load_tile80<128>(sb + OFF_BH, pBh + p * 32, ldb, tid);
        load_tile80<128>(sb + OFF_BL, pBl + p * 32, ldb, tid);
        asm volatile("cp.async.commit_group;" ::: "memory");
    }

    float acc[4][8][4];
    #pragma unroll
    for (int i = 0; i < 4; i++)
        #pragma unroll
        for (int j = 0; j < 8; j++)
            #pragma unroll
            for (int r = 0; r < 4; r++) acc[i][j][r] = 0.f;

    // per-thread fragment base offsets (bytes)
    const uint32_t aoff = (uint32_t)(g * ROWB + t2 * 2);
    const uint32_t boff = (uint32_t)(g * ROWB + t2 * 2);

    int slot = 0;
    for (int k = 0; k < nk; ++k) {
        asm volatile("cp.async.wait_group 1;" ::: "memory");
        __syncthreads();
        if (k + 2 < nk) {
            int s2 = (k + 2) % 3;
            uint32_t sb = sbase + s2 * STAGE_B;
            int ko = (k + 2) * 32;
            load_tile80<256>(sb + OFF_AH, pAh + ko, lda, tid);
            load_tile80<256>(sb + OFF_AL, pAl + ko, lda, tid);
            load_tile80<128>(sb + OFF_BH, pBh + ko, ldb, tid);
            load_tile80<128>(sb + OFF_BL, pBl + ko, ldb, tid);
        }
        asm volatile("cp.async.commit_group;" ::: "memory");

        const uint32_t stg = sbase + slot * STAGE_B;
        const uint32_t A_h = stg + OFF_AH + (uint32_t)(wm * 64) * ROWB + aoff;
        const uint32_t A_l = stg + OFF_AL + (uint32_t)(wm * 64) * ROWB + aoff;
        const uint32_t B_h = stg + OFF_BH + (uint32_t)(wn * 64) * ROWB + boff;
        const uint32_t B_l = stg + OFF_BL + (uint32_t)(wn * 64) * ROWB + boff;

        #pragma unroll
        for (int s = 0; s < 2; ++s) {
            const uint32_t so = (uint32_t)(s * 32);   // 16 elems * 2B
            uint32_t ah[4][4], al_[4][4];
            #pragma unroll
            for (int i = 0; i < 4; ++i) {
                uint32_t base = (uint32_t)(i * 16) * ROWB + so;
                #pragma unroll
                for (int r = 0; r < 4; ++r) {
                    uint32_t o = base + (uint32_t)((r & 1) * 8 * ROWB) + (uint32_t)((r >> 1) * 16);
                    ah[i][r]  = lds32(A_h + o);
                    al_[i][r] = lds32(A_l + o);
                }
            }
            uint32_t bh[8][2], bl_[8][2];
            #pragma unroll
            for (int j = 0; j < 8; ++j) {
                uint32_t base = (uint32_t)(j * 8) * ROWB + so;
                bh[j][0]  = lds32(B_h + base);
                bh[j][1]  = lds32(B_h + base + 16);
                bl_[j][0] = lds32(B_l + base);
                bl_[j][1] = lds32(B_l + base + 16);
            }
            #pragma unroll
            for (int i = 0; i < 4; ++i)
                #pragma unroll
                for (int j = 0; j < 8; ++j) {
                    mma16816(acc[i][j], ah[i],  bh[j]);
                    mma16816(acc[i][j], ah[i],  bl_[j]);
                    mma16816(acc[i][j], al_[i], bh[j]);
                }
        }
        slot = (slot + 1) % 3;
    }

    // ---- Epilogue (direct from registers) ----
    float* Cf_ = (MODE == 2) ? Cf + (size_t)bz * batC : nullptr;
    bf16*  Ch_ = (MODE != 2) ? Ch + (size_t)bz * batC : nullptr;
    bf16*  Cl_ = (MODE != 2) ? Cl + (size_t)bz * batC : nullptr;
    const float* aux2b = (MODE == 3) ? aux2 + (size_t)bz * batAux : nullptr;
    const bf16* Uh_ = (MODE == 1) ? Uh + (size_t)bz * batU : nullptr;
    const bf16* Ul_ = (MODE == 1) ? Ul + (size_t)bz * batU : nullptr;

    #pragma unroll
    for (int i = 0; i < 4; ++i) {
        #pragma unroll
        for (int half = 0; half < 2; ++half) {
            int rowg = tileM + wm * 64 + i * 16 + g + half * 8;
            #pragma unroll
            for (int j = 0; j < 8; ++j) {
                int col = tileN + wn * 64 + j * 8 + t2;
                float v0 = acc[i][j][half * 2 + 0];
                float v1 = acc[i][j][half * 2 + 1];
                if (MODE == 0) {
                    v0 += aux1[col];     v1 += aux1[col + 1];
                    v0 = v0 / (1.f + expf(-v0));
                    v1 = v1 / (1.f + expf(-v1));
                } else if (MODE == 1) {
                    size_t uo = (size_t)rowg * ldU + col;
                    float u0 = __bfloat162float(Uh_[uo])     + __bfloat162float(Ul_[uo]);
                    float u1 = __bfloat162float(Uh_[uo + 1]) + __bfloat162float(Ul_[uo + 1]);
                    v0 *= u0; v1 *= u1;
                } else if (MODE == 2) {
                    size_t ao = (size_t)rowg * ldaux + col;
                    v0 += aux1[col]     + aux2[ao];
                    v1 += aux1[col + 1] + aux2[ao + 1];
                    size_t o = (size_t)rowg * ldc + col;
                    float2 f2 = make_float2(v0, v1);
                    *(float2*)&Cf_[o] = f2;
                    continue;
                } else { // MODE 3
                    float m0 = (1.f - aux2b[col])     * (-1e12f);
                    float m1 = (1.f - aux2b[col + 1]) * (-1e12f);
                    float t0 = v0 * (1.f / 512.f) + aux1[col - rowg + 511]     + m0;
                    float t1 = v1 * (1.f / 512.f) + aux1[col + 1 - rowg + 511] + m1;
                    t0 = fmaxf(t0, 0.f); t1 = fmaxf(t1, 0.f);
                    v0 = t0 * t0; v1 = t1 * t1;
                }
                bf16 h0, l0, h1, l1;
                split2(v0, h0, l0); split2(v1, h1, l1);
                size_t o = (size_t)rowg * ldc + col;
                *(uint32_t*)&Ch_[o] = pack_bf2(h0, h1);
                *(uint32_t*)&Cl_[o] = pack_bf2(l0, l1);
            }
        }
    }
}

// ---------------------------------------------------------------------------
// Launch
// ---------------------------------------------------------------------------
extern "C" void kernel_launch(void* const* d_in, const int* in_sizes, int n_in,
                              void* d_out, int out_size)
{
    const float* x     = (const float*)d_in[0];
    const float* amask = (const float*)d_in[1];
    const float* gamma = (const float*)d_in[2];
    const float* beta  = (const float*)d_in[3];
    const float* w     = (const float*)d_in[4];
    const float* uv_w  = (const float*)d_in[7];
    const float* uv_b  = (const float*)d_in[8];
    const float* o_w   = (const float*)d_in[9];
    const float* o_b   = (const float*)d_in[10];
    const float* ln_g  = (const float*)d_in[11];
    const float* ln_b  = (const float*)d_in[12];
    float* out = (float*)d_out;

    bf16 *xnh, *xnl, *uvwh, *uvwl, *owh, *owl, *uvh, *uvl;
    bf16 *qh, *ql, *kh, *kl, *kerh, *kerl, *vth, *vtl, *atth, *attl;
    float* trig;
    cudaGetSymbolAddress((void**)&xnh,  g_xnh);  cudaGetSymbolAddress((void**)&xnl,  g_xnl);
    cudaGetSymbolAddress((void**)&uvwh, g_uvwh); cudaGetSymbolAddress((void**)&uvwl, g_uvwl);
    cudaGetSymbolAddress((void**)&owh,  g_owh);  cudaGetSymbolAddress((void**)&owl,  g_owl);
    cudaGetSymbolAddress((void**)&uvh,  g_uvh);  cudaGetSymbolAddress((void**)&uvl,  g_uvl);
    cudaGetSymbolAddress((void**)&qh,   g_qh);   cudaGetSymbolAddress((void**)&ql,   g_ql);
    cudaGetSymbolAddress((void**)&kh,   g_kh);   cudaGetSymbolAddress((void**)&kl,   g_kl);
    cudaGetSymbolAddress((void**)&kerh, g_kerh); cudaGetSymbolAddress((void**)&kerl, g_kerl);
    cudaGetSymbolAddress((void**)&vth,  g_vth);  cudaGetSymbolAddress((void**)&vtl,  g_vtl);
    cudaGetSymbolAddress((void**)&atth, g_atth); cudaGetSymbolAddress((void**)&attl, g_attl);
    cudaGetSymbolAddress((void**)&trig, g_trig);

    cudaFuncSetAttribute(mm_kernel<0>, cudaFuncAttributeMaxDynamicSharedMemorySize, SMEM_MM);
    cudaFuncSetAttribute(mm_kernel<1>, cudaFuncAttributeMaxDynamicSharedMemorySize, SMEM_MM);
    cudaFuncSetAttribute(mm_kernel<2>, cudaFuncAttributeMaxDynamicSharedMemorySize, SMEM_MM);
    cudaFuncSetAttribute(mm_kernel<3>, cudaFuncAttributeMaxDynamicSharedMemorySize, SMEM_MM);

    // 1) LN -> split
    ln_kernel<<<MTOT, 256>>>(x, ln_g, ln_b, xnh, xnl);
    // 2) trig table
    trig_kernel<<<(NSEQ * 64 + 255) / 256, 256>>>(trig);
    // 3) weight transpose+split
    tsplit_kernel<<<dim3(NUV / 32, HB / 32), dim3(32, 8)>>>(uv_w, HB, NUV, uvwh, uvwl);
    tsplit_kernel<<<dim3(HB / 32, EB / 32), dim3(32, 8)>>>(o_w, EB, HB, owh, owl);
    // 4) uv = silu(xn @ uv_w + b)  [16384 x 4224, K=1024]
    mm_kernel<0><<<dim3(NUV / 128, MTOT / 256, 1), 256, SMEM_MM>>>(
        xnh, xnl, uvwh, uvwl, HB, HB, HB, NUV, 0, 0, 0,
        nullptr, uvh, uvl, uv_b, nullptr, 0, 0, nullptr, nullptr, 0, 0);
    // 5) q/k build
    qk_kernel<<<MTOT, 128>>>(gamma, beta, trig, uvh, uvl, qh, ql, kh, kl);
    // 6) ker = relu(q@k^T/512 + bias + mask)^2  per batch [512x512, K=128]
    mm_kernel<3><<<dim3(NSEQ / 128, NSEQ / 256, NBATCH), 256, SMEM_MM>>>(
        qh, ql, kh, kl, SB, SB, SB, NSEQ,
        (long)NSEQ * SB, (long)NSEQ * SB, (long)NSEQ * NSEQ,
        nullptr, kerh, kerl, w, amask, (long)NSEQ, 0, nullptr, nullptr, 0, 0);
    // 7) vT transpose
    vtrans_kernel<<<dim3(NSEQ / 32, EB / 32, NBATCH), dim3(32, 8)>>>(uvh, uvl, vth, vtl);
    // 8) att = u * (ker @ v)  per batch [512x2048, K=512]
    mm_kernel<1><<<dim3(EB / 128, NSEQ / 256, NBATCH), 256, SMEM_MM>>>(
        kerh, kerl, vth, vtl, NSEQ, NSEQ, NSEQ, EB,
        (long)NSEQ * NSEQ, (long)EB * NSEQ, (long)NSEQ * EB,
        nullptr, atth, attl, nullptr, nullptr, 0, 0,
        uvh, uvl, (long)NSEQ * NUV, NUV);
    // 9) out = att @ o_w + o_b + x  [16384 x 1024, K=2048]
    mm_kernel<2><<<dim3(HB / 128, MTOT / 256, 1), 256, SMEM_MM>>>(
        atth, attl, owh, owl, EB, EB, EB, HB, 0, 0, 0,
        out, nullptr, nullptr, o_b, x, 0, HB, nullptr, nullptr, 0, 0);
}

// round 12
// speedup vs baseline: 1.8688x; 1.0323x over previous
#include <cuda_runtime.h>
#include <cuda_bf16.h>
#include <math.h>
#include <stdint.h>

#define HB    1024
#define EB    2048
#define SB    128
#define NUV   4224
#define NSEQ  512
#define NBATCH 32
#define MTOT  16384

typedef __nv_bfloat16 bf16;

// ---------------------------------------------------------------------------
// Scratch
// ---------------------------------------------------------------------------
__device__ __align__(128) bf16 g_xnh [(size_t)MTOT * HB];
__device__ __align__(128) bf16 g_xnl [(size_t)MTOT * HB];
__device__ __align__(128) bf16 g_uvwh[(size_t)NUV * HB];
__device__ __align__(128) bf16 g_uvwl[(size_t)NUV * HB];
__device__ __align__(128) bf16 g_owh [(size_t)HB * EB];
__device__ __align__(128) bf16 g_owl [(size_t)HB * EB];
__device__ __align__(128) bf16 g_uvh [(size_t)MTOT * NUV];
__device__ __align__(128) bf16 g_uvl [(size_t)MTOT * NUV];
__device__ __align__(128) bf16 g_qh  [(size_t)MTOT * SB];
__device__ __align__(128) bf16 g_ql  [(size_t)MTOT * SB];
__device__ __align__(128) bf16 g_kh  [(size_t)MTOT * SB];
__device__ __align__(128) bf16 g_kl  [(size_t)MTOT * SB];
__device__ __align__(128) bf16 g_kerh[(size_t)NBATCH * NSEQ * NSEQ];
__device__ __align__(128) bf16 g_kerl[(size_t)NBATCH * NSEQ * NSEQ];
__device__ __align__(128) bf16 g_vth [(size_t)NBATCH * EB * NSEQ];
__device__ __align__(128) bf16 g_vtl [(size_t)NBATCH * EB * NSEQ];
__device__ __align__(128) bf16 g_atth[(size_t)MTOT * EB];
__device__ __align__(128) bf16 g_attl[(size_t)MTOT * EB];
__device__ __align__(128) float g_trig[NSEQ * 64 * 2];

// ---------------------------------------------------------------------------
// Helpers
// ---------------------------------------------------------------------------
__device__ __forceinline__ uint32_t smem_u32(const void* p) {
    uint32_t a;
    asm("{ .reg .u64 t; cvta.to.shared.u64 t, %1; cvt.u32.u64 %0, t; }" : "=r"(a) : "l"(p));
    return a;
}
__device__ __forceinline__ void ldsm4(uint32_t* r, uint32_t a) {
    asm volatile("ldmatrix.sync.aligned.m8n8.x4.shared.b16 {%0,%1,%2,%3}, [%4];"
        : "=r"(r[0]), "=r"(r[1]), "=r"(r[2]), "=r"(r[3]) : "r"(a));
}
__device__ __forceinline__ void mma16816(float* d, const uint32_t* a, const uint32_t* b) {
    asm volatile(
        "mma.sync.aligned.m16n8k16.row.col.f32.bf16.bf16.f32 "
        "{%0,%1,%2,%3}, {%4,%5,%6,%7}, {%8,%9}, {%0,%1,%2,%3};"
        : "+f"(d[0]), "+f"(d[1]), "+f"(d[2]), "+f"(d[3])
        : "r"(a[0]), "r"(a[1]), "r"(a[2]), "r"(a[3]), "r"(b[0]), "r"(b[1]));
}
__device__ __forceinline__ void split2(float v, bf16& h, bf16& l) {
    h = __float2bfloat16(v);
    l = __float2bfloat16(v - __bfloat162float(h));
}
__device__ __forceinline__ uint32_t pack_bf2(bf16 a, bf16 b) {
    return (uint32_t)__bfloat16_as_ushort(a) | ((uint32_t)__bfloat16_as_ushort(b) << 16);
}

// ---------------------------------------------------------------------------
// LayerNorm -> hi/lo bf16
// ---------------------------------------------------------------------------
__global__ void ln_kernel(const float* __restrict__ x, const float* __restrict__ g,
                          const float* __restrict__ b,
                          bf16* __restrict__ oh, bf16* __restrict__ ol)
{
    int row = blockIdx.x;
    float4 v = ((const float4*)(x + (size_t)row * HB))[threadIdx.x];
    float s = v.x + v.y + v.z + v.w;
    float sq = v.x*v.x + v.y*v.y + v.z*v.z + v.w*v.w;
    #pragma unroll
    for (int o = 16; o; o >>= 1) {
        s  += __shfl_xor_sync(0xffffffffu, s, o);
        sq += __shfl_xor_sync(0xffffffffu, sq, o);
    }
    __shared__ float ss[8], sqs[8];
    int w = threadIdx.x >> 5, l = threadIdx.x & 31;
    if (l == 0) { ss[w] = s; sqs[w] = sq; }
    __syncthreads();
    float st = 0.f, sqt = 0.f;
    #pragma unroll
    for (int i = 0; i < 8; i++) { st += ss[i]; sqt += sqs[i]; }
    float mu = st * (1.f / HB);
    float var = sqt * (1.f / HB) - mu * mu;
    float rs = rsqrtf(var + 1e-5f);
    float4 gg = ((const float4*)g)[threadIdx.x];
    float4 bb = ((const float4*)b)[threadIdx.x];
    float vv[4] = {v.x, v.y, v.z, v.w};
    float gv[4] = {gg.x, gg.y, gg.z, gg.w};
    float bv[4] = {bb.x, bb.y, bb.z, bb.w};
    size_t base = (size_t)row * HB + threadIdx.x * 4;
    #pragma unroll
    for (int j = 0; j < 4; j++) {
        float o = (vv[j] - mu) * rs * gv[j] + bv[j];
        bf16 h, lo; split2(o, h, lo);
        oh[base + j] = h; ol[base + j] = lo;
    }
}

// ---------------------------------------------------------------------------
// RoPE trig table
// ---------------------------------------------------------------------------
__global__ void trig_kernel(float* __restrict__ tab)
{
    int idx = blockIdx.x * blockDim.x + threadIdx.x;
    if (idx >= NSEQ * 64) return;
    int n = idx >> 6, i = idx & 63;
    double inv = pow(10000.0, (double)i * (1.0 / 64.0));
    float arg = (float)n * (float)inv;
    tab[2 * idx]     = (float)cos((double)arg);
    tab[2 * idx + 1] = (float)sin((double)arg);
}

// ---------------------------------------------------------------------------
// Weight transpose + split: W[K,N] f32 -> T[N,K] hi/lo bf16
// ---------------------------------------------------------------------------
__global__ void tsplit_kernel(const float* __restrict__ W, int K, int N,
                              bf16* __restrict__ Th, bf16* __restrict__ Tl)
{
    __shared__ float t[32][33];
    int n0 = blockIdx.x * 32, k0 = blockIdx.y * 32;
    int tx = threadIdx.x, ty = threadIdx.y;
    #pragma unroll
    for (int i = 0; i < 32; i += 8)
        t[ty + i][tx] = W[(size_t)(k0 + ty + i) * N + (n0 + tx)];
    __syncthreads();
    #pragma unroll
    for (int i = 0; i < 32; i += 8) {
        float v = t[tx][ty + i];
        bf16 h, l; split2(v, h, l);
        size_t o = (size_t)(n0 + ty + i) * K + (k0 + tx);
        Th[o] = h; Tl[o] = l;
    }
}

// ---------------------------------------------------------------------------
// v transpose (bf16 hi/lo): uv[:, E:2E] per batch -> vT[b][e][s]
// ---------------------------------------------------------------------------
__global__ void vtrans_kernel(const bf16* __restrict__ uvh, const bf16* __restrict__ uvl,
                              bf16* __restrict__ vTh, bf16* __restrict__ vTl)
{
    __shared__ bf16 th[32][33], tl[32][33];
    int b = blockIdx.z;
    int s0 = blockIdx.x * 32, e0 = blockIdx.y * 32;
    int tx = threadIdx.x, ty = threadIdx.y;
    #pragma unroll
    for (int i = 0; i < 32; i += 8) {
        size_t src = ((size_t)(b * NSEQ + s0 + ty + i)) * NUV + EB + e0 + tx;
        th[ty + i][tx] = uvh[src];
        tl[ty + i][tx] = uvl[src];
    }
    __syncthreads();
    #pragma unroll
    for (int i = 0; i < 32; i += 8) {
        size_t dst = ((size_t)b * EB + e0 + ty + i) * NSEQ + (s0 + tx);
        vTh[dst] = th[tx][ty + i];
        vTl[dst] = tl[tx][ty + i];
    }
}

// ---------------------------------------------------------------------------
// q/k build with gamma/beta + RoPE -> hi/lo bf16
// ---------------------------------------------------------------------------
__global__ void qk_kernel(const float* __restrict__ gamma, const float* __restrict__ beta,
                          const float* __restrict__ trig,
                          const bf16* __restrict__ uvh, const bf16* __restrict__ uvl,
                          bf16* __restrict__ qh, bf16* __restrict__ ql,
                          bf16* __restrict__ kh, bf16* __restrict__ kl)
{
    int p = blockIdx.x;
    int n = p & (NSEQ - 1);
    int d = threadIdx.x;
    __shared__ float sb[SB];
    size_t src = (size_t)p * NUV + 2 * EB + d;
    sb[d] = __bfloat162float(uvh[src]) + __bfloat162float(uvl[src]);
    __syncthreads();
    int i = d & 63;
    float c = trig[2 * (n * 64 + i)];
    float s = trig[2 * (n * 64 + i) + 1];
    int dp = d ^ 64;
    float own_q = sb[d]  * gamma[d]       + beta[d];
    float par_q = sb[dp] * gamma[dp]      + beta[dp];
    float own_k = sb[d]  * gamma[128 + d]  + beta[128 + d];
    float par_k = sb[dp] * gamma[128 + dp] + beta[128 + dp];
    float qv, kv;
    if (d < 64) { qv = own_q * c - par_q * s; kv = own_k * c - par_k * s; }
    else        { qv = own_q * c + par_q * s; kv = own_k * c + par_k * s; }
    size_t o = (size_t)p * SB + d;
    bf16 h, l;
    split2(qv, h, l); qh[o] = h; ql[o] = l;
    split2(kv, h, l); kh[o] = h; kl[o] = l;
}

// ---------------------------------------------------------------------------
// Split-bf16 GEMM via mma.sync (HMMA) + ldmatrix fragment loads.
// CTA 256x128, BK=32, 8 warps (4Mx2N), warp tile 64x64. 3-stage cp.async.
// ---------------------------------------------------------------------------
#define ROWB 80
#define OFF_AH 0
#define OFF_AL (256 * ROWB)
#define OFF_BH (512 * ROWB)
#define OFF_BL (640 * ROWB)
#define STAGE_B (768 * ROWB)
#define SMEM_MM (3 * STAGE_B)

template<int R>
__device__ __forceinline__ void load_tile80(uint32_t sdst, const bf16* gp, int ld, int tid)
{
    #pragma unroll
    for (int it = 0; it < R * 4 / 256; ++it) {
        int idx = it * 256 + tid;
        int row = idx >> 2, c = idx & 3;
        asm volatile("cp.async.cg.shared.global [%0], [%1], 16;"
            :: "r"(sdst + row * ROWB + c * 16), "l"(gp + (size_t)row * ld + c * 8));
    }
}

template<int MODE>
__global__ __launch_bounds__(256, 1)
void mm_kernel(const bf16* __restrict__ Ah, const bf16* __restrict__ Al,
               const bf16* __restrict__ Bh, const bf16* __restrict__ Bl,
               int Kd, int lda, int ldb, int ldc,
               long batA, long batB, long batC,
               float* __restrict__ Cf, bf16* __restrict__ Ch, bf16* __restrict__ Cl,
               const float* __restrict__ aux1, const float* __restrict__ aux2,
               long batAux, int ldaux,
               const bf16* __restrict__ Uh, const bf16* __restrict__ Ul,
               long batU, int ldU)
{
    extern __shared__ __align__(128) char smem[];
    const uint32_t sbase = smem_u32(smem);
    const int tid = threadIdx.x, lane = tid & 31, w = tid >> 5;
    const int wm = w >> 1, wn = w & 1;
    const int g = lane >> 2, t2 = (lane & 3) * 2;
    const int bz = blockIdx.z;
    const int tileM = blockIdx.y * 256, tileN = blockIdx.x * 128;

    const bf16* pAh = Ah + (size_t)bz * batA + (size_t)tileM * lda;
    const bf16* pAl = Al + (size_t)bz * batA + (size_t)tileM * lda;
    const bf16* pBh = Bh + (size_t)bz * batB + (size_t)tileN * ldb;
    const bf16* pBl = Bl + (size_t)bz * batB + (size_t)tileN * ldb;

    const int nk = Kd / 32;

    // prologue: stages 0,1
    #pragma unroll
    for (int p = 0; p < 2; ++p) {
        uint32_t sb = sbase + p * STAGE_B;
        load_tile80<256>(sb + OFF_AH, pAh + p * 32, lda, tid);
        load_tile80<256>(sb + OFF_AL, pAl + p * 32, lda, tid);
        load_tile80<128>(sb + OFF_BH, pBh + p * 32, ldb, tid);
        load_tile80<128>(sb + OFF_BL, pBl + p * 32, ldb, tid);
        asm volatile("cp.async.commit_group;" ::: "memory");
    }

    float acc[4][8][4];
    #pragma unroll
    for (int i = 0; i < 4; i++)
        #pragma unroll
        for (int j = 0; j < 8; j++)
            #pragma unroll
            for (int r = 0; r < 4; r++) acc[i][j][r] = 0.f;

    // ldmatrix per-lane offsets
    const int q8 = lane >> 3, i8 = lane & 7;
    const uint32_t laneA = (uint32_t)(((q8 & 1) * 8 + i8) * ROWB + (q8 >> 1) * 16);
    const uint32_t laneB = (uint32_t)(((q8 >> 1) * 8 + i8) * ROWB + (q8 & 1) * 16);

    int slot = 0;
    for (int k = 0; k < nk; ++k) {
        asm volatile("cp.async.wait_group 1;" ::: "memory");
        __syncthreads();
        if (k + 2 < nk) {
            int s2 = (k + 2) % 3;
            uint32_t sb = sbase + s2 * STAGE_B;
            int ko = (k + 2) * 32;
            load_tile80<256>(sb + OFF_AH, pAh + ko, lda, tid);
            load_tile80<256>(sb + OFF_AL, pAl + ko, lda, tid);
            load_tile80<128>(sb + OFF_BH, pBh + ko, ldb, tid);
            load_tile80<128>(sb + OFF_BL, pBl + ko, ldb, tid);
        }
        asm volatile("cp.async.commit_group;" ::: "memory");

        const uint32_t stg = sbase + slot * STAGE_B;
        const uint32_t A_h = stg + OFF_AH + (uint32_t)(wm * 64) * ROWB + laneA;
        const uint32_t A_l = stg + OFF_AL + (uint32_t)(wm * 64) * ROWB + laneA;
        const uint32_t B_h = stg + OFF_BH + (uint32_t)(wn * 64) * ROWB + laneB;
        const uint32_t B_l = stg + OFF_BL + (uint32_t)(wn * 64) * ROWB + laneB;

        #pragma unroll
        for (int s = 0; s < 2; ++s) {
            const uint32_t so = (uint32_t)(s * 32);
            uint32_t ah[4][4], al_[4][4];
            #pragma unroll
            for (int i = 0; i < 4; ++i) {
                ldsm4(ah[i],  A_h + (uint32_t)(i * 16) * ROWB + so);
                ldsm4(al_[i], A_l + (uint32_t)(i * 16) * ROWB + so);
            }
            uint32_t bh[4][4], bl_[4][4];   // [p]: regs {b0(j=2p), b1(j=2p), b0(j=2p+1), b1(j=2p+1)}
            #pragma unroll
            for (int p = 0; p < 4; ++p) {
                ldsm4(bh[p],  B_h + (uint32_t)(p * 16) * ROWB + so);
                ldsm4(bl_[p], B_l + (uint32_t)(p * 16) * ROWB + so);
            }
            #pragma unroll
            for (int i = 0; i < 4; ++i)
                #pragma unroll
                for (int j = 0; j < 8; ++j) {
                    const uint32_t* bhp = &bh[j >> 1][(j & 1) * 2];
                    const uint32_t* blp = &bl_[j >> 1][(j & 1) * 2];
                    mma16816(acc[i][j], ah[i],  bhp);
                    mma16816(acc[i][j], ah[i],  blp);
                    mma16816(acc[i][j], al_[i], bhp);
                }
        }
        slot = (slot + 1) % 3;
    }

    // ---- Epilogue (direct from registers) ----
    float* Cf_ = (MODE == 2) ? Cf + (size_t)bz * batC : nullptr;
    bf16*  Ch_ = (MODE != 2) ? Ch + (size_t)bz * batC : nullptr;
    bf16*  Cl_ = (MODE != 2) ? Cl + (size_t)bz * batC : nullptr;
    const float* aux2b = (MODE == 3) ? aux2 + (size_t)bz * batAux : nullptr;
    const bf16* Uh_ = (MODE == 1) ? Uh + (size_t)bz * batU : nullptr;
    const bf16* Ul_ = (MODE == 1) ? Ul + (size_t)bz * batU : nullptr;

    #pragma unroll
    for (int i = 0; i < 4; ++i) {
        #pragma unroll
        for (int half = 0; half < 2; ++half) {
            int rowg = tileM + wm * 64 + i * 16 + g + half * 8;
            #pragma unroll
            for (int j = 0; j < 8; ++j) {
                int col = tileN + wn * 64 + j * 8 + t2;
                float v0 = acc[i][j][half * 2 + 0];
                float v1 = acc[i][j][half * 2 + 1];
                if (MODE == 0) {
                    v0 += aux1[col];     v1 += aux1[col + 1];
                    v0 = v0 / (1.f + expf(-v0));
                    v1 = v1 / (1.f + expf(-v1));
                } else if (MODE == 1) {
                    size_t uo = (size_t)rowg * ldU + col;
                    float u0 = __bfloat162float(Uh_[uo])     + __bfloat162float(Ul_[uo]);
                    float u1 = __bfloat162float(Uh_[uo + 1]) + __bfloat162float(Ul_[uo + 1]);
                    v0 *= u0; v1 *= u1;
                } else if (MODE == 2) {
                    size_t ao = (size_t)rowg * ldaux + col;
                    v0 += aux1[col]     + aux2[ao];
                    v1 += aux1[col + 1] + aux2[ao + 1];
                    size_t o = (size_t)rowg * ldc + col;
                    float2 f2 = make_float2(v0, v1);
                    *(float2*)&Cf_[o] = f2;
                    continue;
                } else { // MODE 3
                    float m0 = (1.f - aux2b[col])     * (-1e12f);
                    float m1 = (1.f - aux2b[col + 1]) * (-1e12f);
                    float t0 = v0 * (1.f / 512.f) + aux1[col - rowg + 511]     + m0;
                    float t1 = v1 * (1.f / 512.f) + aux1[col + 1 - rowg + 511] + m1;
                    t0 = fmaxf(t0, 0.f); t1 = fmaxf(t1, 0.f);
                    v0 = t0 * t0; v1 = t1 * t1;
                }
                bf16 h0, l0, h1, l1;
                split2(v0, h0, l0); split2(v1, h1, l1);
                size_t o = (size_t)rowg * ldc + col;
                *(uint32_t*)&Ch_[o] = pack_bf2(h0, h1);
                *(uint32_t*)&Cl_[o] = pack_bf2(l0, l1);
            }
        }
    }
}

// ---------------------------------------------------------------------------
// Launch (order arranged so mm_kernel<0> is the 4th launch -> gets profiled)
// ---------------------------------------------------------------------------
extern "C" void kernel_launch(void* const* d_in, const int* in_sizes, int n_in,
                              void* d_out, int out_size)
{
    const float* x     = (const float*)d_in[0];
    const float* amask = (const float*)d_in[1];
    const float* gamma = (const float*)d_in[2];
    const float* beta  = (const float*)d_in[3];
    const float* w     = (const float*)d_in[4];
    const float* uv_w  = (const float*)d_in[7];
    const float* uv_b  = (const float*)d_in[8];
    const float* o_w   = (const float*)d_in[9];
    const float* o_b   = (const float*)d_in[10];
    const float* ln_g  = (const float*)d_in[11];
    const float* ln_b  = (const float*)d_in[12];
    float* out = (float*)d_out;

    bf16 *xnh, *xnl, *uvwh, *uvwl, *owh, *owl, *uvh, *uvl;
    bf16 *qh, *ql, *kh, *kl, *kerh, *kerl, *vth, *vtl, *atth, *attl;
    float* trig;
    cudaGetSymbolAddress((void**)&xnh,  g_xnh);  cudaGetSymbolAddress((void**)&xnl,  g_xnl);
    cudaGetSymbolAddress((void**)&uvwh, g_uvwh); cudaGetSymbolAddress((void**)&uvwl, g_uvwl);
    cudaGetSymbolAddress((void**)&owh,  g_owh);  cudaGetSymbolAddress((void**)&owl,  g_owl);
    cudaGetSymbolAddress((void**)&uvh,  g_uvh);  cudaGetSymbolAddress((void**)&uvl,  g_uvl);
    cudaGetSymbolAddress((void**)&qh,   g_qh);   cudaGetSymbolAddress((void**)&ql,   g_ql);
    cudaGetSymbolAddress((void**)&kh,   g_kh);   cudaGetSymbolAddress((void**)&kl,   g_kl);
    cudaGetSymbolAddress((void**)&kerh, g_kerh); cudaGetSymbolAddress((void**)&kerl, g_kerl);
    cudaGetSymbolAddress((void**)&vth,  g_vth);  cudaGetSymbolAddress((void**)&vtl,  g_vtl);
    cudaGetSymbolAddress((void**)&atth, g_atth); cudaGetSymbolAddress((void**)&attl, g_attl);
    cudaGetSymbolAddress((void**)&trig, g_trig);

    cudaFuncSetAttribute(mm_kernel<0>, cudaFuncAttributeMaxDynamicSharedMemorySize, SMEM_MM);
    cudaFuncSetAttribute(mm_kernel<1>, cudaFuncAttributeMaxDynamicSharedMemorySize, SMEM_MM);
    cudaFuncSetAttribute(mm_kernel<2>, cudaFuncAttributeMaxDynamicSharedMemorySize, SMEM_MM);
    cudaFuncSetAttribute(mm_kernel<3>, cudaFuncAttributeMaxDynamicSharedMemorySize, SMEM_MM);

    // 1) LN -> split
    ln_kernel<<<MTOT, 256>>>(x, ln_g, ln_b, xnh, xnl);
    // 2,3) weight transpose+split
    tsplit_kernel<<<dim3(NUV / 32, HB / 32), dim3(32, 8)>>>(uv_w, HB, NUV, uvwh, uvwl);
    tsplit_kernel<<<dim3(HB / 32, EB / 32), dim3(32, 8)>>>(o_w, EB, HB, owh, owl);
    // 4) uv = silu(xn @ uv_w + b)  [16384 x 4224, K=1024]   <-- profiled slot
    mm_kernel<0><<<dim3(NUV / 128, MTOT / 256, 1), 256, SMEM_MM>>>(
        xnh, xnl, uvwh, uvwl, HB, HB, HB, NUV, 0, 0, 0,
        nullptr, uvh, uvl, uv_b, nullptr, 0, 0, nullptr, nullptr, 0, 0);
    // 5) trig table
    trig_kernel<<<(NSEQ * 64 + 255) / 256, 256>>>(trig);
    // 6) q/k build
    qk_kernel<<<MTOT, 128>>>(gamma, beta, trig, uvh, uvl, qh, ql, kh, kl);
    // 7) ker = relu(q@k^T/512 + bias + mask)^2  per batch [512x512, K=128]
    mm_kernel<3><<<dim3(NSEQ / 128, NSEQ / 256, NBATCH), 256, SMEM_MM>>>(
        qh, ql, kh, kl, SB, SB, SB, NSEQ,
        (long)NSEQ * SB, (long)NSEQ * SB, (long)NSEQ * NSEQ,
        nullptr, kerh, kerl, w, amask, (long)NSEQ, 0, nullptr, nullptr, 0, 0);
    // 8) vT transpose
    vtrans_kernel<<<dim3(NSEQ / 32, EB / 32, NBATCH), dim3(32, 8)>>>(uvh, uvl, vth, vtl);
    // 9) att = u * (ker @ v)  per batch [512x2048, K=512]
    mm_kernel<1><<<dim3(EB / 128, NSEQ / 256, NBATCH), 256, SMEM_MM>>>(
        kerh, kerl, vth, vtl, NSEQ, NSEQ, NSEQ, EB,
        (long)NSEQ * NSEQ, (long)EB * NSEQ, (long)NSEQ * EB,
        nullptr, atth, attl, nullptr, nullptr, 0, 0,
        uvh, uvl, (long)NSEQ * NUV, NUV);
    // 10) out = att @ o_w + o_b + x  [16384 x 1024, K=2048]
    mm_kernel<2><<<dim3(HB / 128, MTOT / 256, 1), 256, SMEM_MM>>>(
        atth, attl, owh, owl, EB, EB, EB, HB, 0, 0, 0,
        out, nullptr, nullptr, o_b, x, 0, HB, nullptr, nullptr, 0, 0);
}